// round 5
// baseline (speedup 1.0000x reference)
#include <cuda_runtime.h>

// Problem constants
#define BB   4
#define CC   16
#define HH   64
#define WW   64
#define FF   32
#define K2   9

// Repacked coefficients: [c][k][g][f] float4
//   g=0: {n0,n1,n2,n3}   g=1: {n4,n5,d0,d1}   g=2: {d2,d3,0,0}
__device__ float4 g_coef4[CC * K2 * 3 * FF];   // 13824 float4 = 221 KB

__device__ __forceinline__ float rcp_fast(float q) {
    float r; asm("rcp.approx.f32 %0, %1;" : "=f"(r) : "f"(q)); return r;
}

// ---------------------------------------------------------------------------
// Kernel 1: repack coefficients
// ---------------------------------------------------------------------------
__global__ void repack_coefs_kernel(const float* __restrict__ nums,
                                    const float* __restrict__ denoms) {
    int idx = blockIdx.x * blockDim.x + threadIdx.x;
    const int total = CC * K2 * 3 * FF;
    if (idx >= total) return;
    int f = idx & (FF - 1);
    int g = (idx >> 5) % 3;
    int k = (idx >> 5) / 3 % K2;
    int c = idx / (FF * 3 * K2);
    const float* np = nums   + (((f * CC + c) * K2) + k) * 6;
    const float* dp = denoms + (((f * CC + c) * K2) + k) * 4;
    float4 v;
    if (g == 0)      v = make_float4(np[0], np[1], np[2], np[3]);
    else if (g == 1) v = make_float4(np[4], np[5], dp[0], dp[1]);
    else             v = make_float4(dp[2], dp[3], 0.f, 0.f);
    g_coef4[idx] = v;
}

// ---------------------------------------------------------------------------
// Kernel 2: rational (Pade) conv.
//   grid  = (2 c-halves, H, B) = (2, 64, 4) = 512 blocks
//   block = 256 threads = 8 warps; lane = f; warp -> 8 consecutive pixels
//   Each block handles 8 input channels for one full 64-wide output row,
//   contributions combined via atomicAdd (exactly 2 per element).
// ---------------------------------------------------------------------------
__global__ __launch_bounds__(256)
void rational_conv_kernel(const float* __restrict__ x, float* __restrict__ out) {
    // halo tile: 8 channels x 3 rows x 66 cols (row padded to 68 for alignment)
    __shared__ __align__(16) float xs[8][3][68];

    const int chalf = blockIdx.x;          // 0 or 1
    const int h     = blockIdx.y;
    const int b     = blockIdx.z;
    const int c0    = chalf * 8;
    const int tid   = threadIdx.x;
    const int lane  = tid & 31;            // f
    const int warp  = tid >> 5;            // 0..7
    const int px0   = warp * 8;            // pixel offset in row

    // --- Load input halo: channels c0..c0+7, rows h-1..h+1, cols -1..64
    for (int i = tid; i < 8 * 3 * 66; i += 256) {
        int j  = i % 66;
        int r  = (i / 66) % 3;
        int cc = i / 198;
        int hh = h - 1 + r;
        int ww = j - 1;
        float v = 0.0f;
        if (hh >= 0 && hh < HH && ww >= 0 && ww < WW)
            v = x[((b * CC + c0 + cc) * HH + hh) * WW + ww];
        xs[cc][r][j] = v;
    }
    __syncthreads();

    float acc[8];
    #pragma unroll
    for (int i = 0; i < 8; ++i) acc[i] = 0.0f;

    #pragma unroll 1
    for (int cc = 0; cc < 8; ++cc) {
        const float4* cbase = g_coef4 + ((c0 + cc) * K2) * 3 * FF + lane;
        #pragma unroll
        for (int a = 0; a < 3; ++a) {
            // 10-tap x window in registers: 3 vector LDS (broadcast)
            const float* xrow = &xs[cc][a][px0];
            float4 xA = *reinterpret_cast<const float4*>(xrow);
            float4 xB = *reinterpret_cast<const float4*>(xrow + 4);
            float2 xC = *reinterpret_cast<const float2*>(xrow + 8);
            float xr[10] = {xA.x, xA.y, xA.z, xA.w,
                            xB.x, xB.y, xB.z, xB.w,
                            xC.x, xC.y};
            #pragma unroll
            for (int bb = 0; bb < 3; ++bb) {
                const int k = a * 3 + bb;
                // 3 coalesced LDG.128 (L1/L2-resident coeff table)
                const float4* cp = cbase + k * 3 * FF;
                const float4 A = __ldg(cp);
                const float4 Bv = __ldg(cp + FF);
                const float4 Cv = __ldg(cp + 2 * FF);
                const float n0 = A.x,  n1 = A.y,  n2 = A.z,  n3 = A.w;
                const float n4 = Bv.x, n5 = Bv.y, d0 = Bv.z, d1 = Bv.w;
                const float d2 = Cv.x, d3 = Cv.y;
                #pragma unroll
                for (int i = 0; i < 8; ++i) {
                    const float xv = xr[i + bb];
                    // P(x): Horner, 5 FMA
                    float p = fmaf(xv, n5, n4);
                    p = fmaf(xv, p, n3);
                    p = fmaf(xv, p, n2);
                    p = fmaf(xv, p, n1);
                    p = fmaf(xv, p, n0);
                    // S(x) = x*(d0 + d1 x + d2 x^2 + d3 x^3)
                    float s = fmaf(xv, d3, d2);
                    s = fmaf(xv, s, d1);
                    s = fmaf(xv, s, d0);
                    s *= xv;
                    const float q = 1.0f + fabsf(s);
                    acc[i] = fmaf(p, rcp_fast(q), acc[i]);
                }
            }
        }
    }

    // --- Combine: exactly 2 contributions per output element (deterministic)
    float* op = out + ((b * FF + lane) * HH + h) * WW + px0;
    #pragma unroll
    for (int i = 0; i < 8; ++i)
        atomicAdd(op + i, acc[i]);
}

// ---------------------------------------------------------------------------
// Launch
// ---------------------------------------------------------------------------
extern "C" void kernel_launch(void* const* d_in, const int* in_sizes, int n_in,
                              void* d_out, int out_size) {
    const float* x      = (const float*)d_in[0];   // (4,16,64,64)
    const float* nums   = (const float*)d_in[1];   // (32,16,3,3,6)
    const float* denoms = (const float*)d_in[2];   // (32,16,3,3,4)
    float* out = (float*)d_out;                    // (4,32,64,64)

    const int total = CC * K2 * 3 * FF;
    repack_coefs_kernel<<<(total + 255) / 256, 256>>>(nums, denoms);
    cudaMemsetAsync(d_out, 0, (size_t)out_size * sizeof(float), 0);

    dim3 grid(2, HH, BB);
    rational_conv_kernel<<<grid, 256>>>(x, out);
}